// round 5
// baseline (speedup 1.0000x reference)
#include <cuda_runtime.h>

// LocalAttention rollout: 10 independent obs steps + 50 sequential pred steps.
// One fused kernel per step. CTA = 16x16 patch tile (+halo) for one batch.
// All activations staged in shared memory transposed [dim][token] (pitch 325,
// odd -> conflict-free for both strided stores and token-contiguous gathers).
// fp32 throughout; packed fma.rn.f32x2 for the weight matvecs.

namespace {

constexpr int NSIDE = 64;
constexpr int P     = NSIDE * NSIDE;   // 4096 patches
constexpr int NB    = 8;               // batch
constexpr int H     = 32;              // hidden
constexpr int E     = 34;              // embed (H + 2 label dims)
constexpr size_t NSTR = (size_t)NB * P * H;   // elems per step slab (1,048,576)

constexpr int TIL    = 16;             // tile side (patches)
constexpr int HT     = TIL + 2;        // halo side = 18
constexpr int TOKENS = HT * HT;        // 324 halo tokens
constexpr int PITCH  = 325;            // odd pitch: conflict-free smem

// shared-memory layout (floats)
constexpr int OFF_TOK = 0;                         // [34][325] token (h + label)
constexpr int OFF_K   = OFF_TOK + E * PITCH;       // [34][325] keys
constexpr int OFF_V   = OFF_K   + E * PITCH;       // [34][325] values
constexpr int OFF_IPW = OFF_V   + E * PITCH;       // in_proj_w (102x34)
constexpr int OFF_IPB = OFF_IPW + 3 * E * E;       // in_proj_b (102)
constexpr int OFF_OPW = OFF_IPB + 3 * E;           // out_proj_w (34x34)
constexpr int OFF_OPB = OFF_OPW + E * E;           // out_proj_b (34)
constexpr int OFF_SAW = OFF_OPB + E;               // fc_sa_w (32x34)
constexpr int OFF_SAB = OFF_SAW + H * E;           // fc_sa_b (32)
constexpr int OFF_F2W = OFF_SAB + H;               // fc2_w (32x32)
constexpr int OFF_F2B = OFF_F2W + H * H;           // fc2_b (32)
constexpr int OFF_LNG = OFF_F2B + H;               // ln gamma (32)
constexpr int OFF_LNB = OFF_LNG + H;               // ln beta (32)
constexpr int SMEM_FLOATS = OFF_LNB + H;           // 40150 floats
constexpr size_t SMEM_BYTES = (size_t)SMEM_FLOATS * sizeof(float); // ~160.6 KB

// packed dual-FMA (Blackwell f32x2 path — ptxas never emits this from C++)
__device__ __forceinline__ float2 ffma2(float2 a, float2 b, float2 c) {
    float2 d;
    asm("fma.rn.f32x2 %0, %1, %2, %3;"
        : "=l"(reinterpret_cast<unsigned long long&>(d))
        : "l"(reinterpret_cast<unsigned long long&>(a)),
          "l"(reinterpret_cast<unsigned long long&>(b)),
          "l"(reinterpret_cast<unsigned long long&>(c)));
    return d;
}

// dot of 34-float weight row (smem, 8B-aligned) with packed register vector
__device__ __forceinline__ float dot17(const float* w, const float2* v) {
    const float2* w2 = reinterpret_cast<const float2*>(w);
    float2 a0 = make_float2(0.f, 0.f), a1 = make_float2(0.f, 0.f);
#pragma unroll
    for (int i = 0; i < 16; i += 2) {
        a0 = ffma2(w2[i],     v[i],     a0);
        a1 = ffma2(w2[i + 1], v[i + 1], a1);
    }
    a0 = ffma2(w2[16], v[16], a0);
    return (a0.x + a1.x) + (a0.y + a1.y);
}

// dot of 32-float weight row with packed register vector
__device__ __forceinline__ float dot16(const float* w, const float2* v) {
    const float2* w2 = reinterpret_cast<const float2*>(w);
    float2 a0 = make_float2(0.f, 0.f), a1 = make_float2(0.f, 0.f);
#pragma unroll
    for (int i = 0; i < 16; i += 2) {
        a0 = ffma2(w2[i],     v[i],     a0);
        a1 = ffma2(w2[i + 1], v[i + 1], a1);
    }
    return (a0.x + a1.x) + (a0.y + a1.y);
}

__device__ __forceinline__ int clamp63(int v) {
    return v < 0 ? 0 : (v > NSIDE - 1 ? NSIDE - 1 : v);
}

__global__ void __launch_bounds__(256, 1)
la_step(const float* __restrict__ src, float* __restrict__ dst,
        const float* __restrict__ g_ipw, const float* __restrict__ g_ipb,
        const float* __restrict__ g_opw, const float* __restrict__ g_opb,
        const float* __restrict__ g_saw, const float* __restrict__ g_sab,
        const float* __restrict__ g_f2w, const float* __restrict__ g_f2b,
        const float* __restrict__ g_lng, const float* __restrict__ g_lnb)
{
    extern __shared__ float sm[];
    const int tid = threadIdx.x;
    src += (size_t)blockIdx.z * NSTR;
    dst += (size_t)blockIdx.z * NSTR;
    const int bb = blockIdx.y;
    const int tr = (int)(blockIdx.x >> 2) * TIL;   // tile origin row
    const int tc = (int)(blockIdx.x & 3) * TIL;    // tile origin col

    // ---- stage weights ----
#pragma unroll 1
    for (int i = tid; i < 3 * E * E; i += 256) sm[OFF_IPW + i] = g_ipw[i];
#pragma unroll 1
    for (int i = tid; i < E * E; i += 256)     sm[OFF_OPW + i] = g_opw[i];
#pragma unroll 1
    for (int i = tid; i < H * E; i += 256)     sm[OFF_SAW + i] = g_saw[i];
#pragma unroll 1
    for (int i = tid; i < H * H; i += 256)     sm[OFF_F2W + i] = g_f2w[i];
    if (tid < 3 * E) sm[OFF_IPB + tid] = g_ipb[tid];
    if (tid < E)     sm[OFF_OPB + tid] = g_opb[tid];
    if (tid < H) {
        sm[OFF_SAB + tid] = g_sab[tid];
        sm[OFF_F2B + tid] = g_f2b[tid];
        sm[OFF_LNG + tid] = g_lng[tid];
        sm[OFF_LNB + tid] = g_lnb[tid];
    }

    // ---- load halo tokens (h + labels) into transposed smem ----
    const float* srcb = src + (size_t)bb * P * H;
#pragma unroll 1
    for (int j = tid; j < TOKENS * H; j += 256) {
        int t = j >> 5, d = j & 31;
        int hr = t / HT, hc = t - hr * HT;
        int gr = clamp63(tr - 1 + hr);
        int gc = clamp63(tc - 1 + hc);
        sm[OFF_TOK + d * PITCH + t] = srcb[(size_t)(gr * NSIDE + gc) * H + d];
    }
#pragma unroll 1
    for (int t = tid; t < TOKENS; t += 256) {
        int hr = t / HT, hc = t - hr * HT;
        int gr = clamp63(tr - 1 + hr);
        int gc = clamp63(tc - 1 + hc);
        sm[OFF_TOK + 32 * PITCH + t] = (float)gr * (1.f / 64.f);
        sm[OFF_TOK + 33 * PITCH + t] = (float)gc * (1.f / 64.f);
    }
    __syncthreads();

    // ---- phase 1: K, V for every halo token (shared across 9 patches) ----
#pragma unroll 1
    for (int t = tid; t < TOKENS; t += 256) {
        float2 tp[17];
#pragma unroll
        for (int i = 0; i < 17; i++) {
            tp[i].x = sm[OFF_TOK + (2 * i) * PITCH + t];
            tp[i].y = sm[OFF_TOK + (2 * i + 1) * PITCH + t];
        }
#pragma unroll 1
        for (int o = 0; o < E; o++) {
            float kk = sm[OFF_IPB + E + o]     + dot17(sm + OFF_IPW + (E + o) * E, tp);
            float vv = sm[OFF_IPB + 2 * E + o] + dot17(sm + OFF_IPW + (2 * E + o) * E, tp);
            sm[OFF_K + o * PITCH + t] = kk;
            sm[OFF_V + o * PITCH + t] = vv;
        }
    }
    __syncthreads();

    // ---- phase 2: one thread per patch ----
    const int pr = tid >> 4, pc = tid & 15;
    const int gr = tr + pr, gc = tc + pc;
    // boundary-corrected neighborhood shift (matches nr[0]+=1 / nr[-1]-=1 etc.)
    const int sr = (gr == 0) - (gr == NSIDE - 1);
    const int sc = (gc == 0) - (gc == NSIDE - 1);
    int nt[9];
#pragma unroll
    for (int dr = 0; dr < 3; dr++)
#pragma unroll
        for (int dc = 0; dc < 3; dc++)
            nt[dr * 3 + dc] = (pr + dr + sr) * HT + (pc + dc + sc);
    const int ct = nt[4];   // shifted center token (query source)

    // q-source token into registers (packed)
    float2 cp[17];
#pragma unroll
    for (int i = 0; i < 17; i++) {
        cp[i].x = sm[OFF_TOK + (2 * i) * PITCH + ct];
        cp[i].y = sm[OFF_TOK + (2 * i + 1) * PITCH + ct];
    }

    // scores fused with q computation: s[t] = sum_o q_o * K[o][nt_t]
    float s[9];
#pragma unroll
    for (int t = 0; t < 9; t++) s[t] = 0.f;
#pragma unroll 1
    for (int o = 0; o < E; o++) {
        float qo = sm[OFF_IPB + o] + dot17(sm + OFF_IPW + o * E, cp);
#pragma unroll
        for (int t = 0; t < 9; t++) s[t] += qo * sm[OFF_K + o * PITCH + nt[t]];
    }

    // softmax over 9 (scaled by 1/sqrt(34))
    constexpr float ISQ = 0.17149858514250882f;
    float mx = -1e30f;
#pragma unroll
    for (int t = 0; t < 9; t++) { s[t] *= ISQ; mx = fmaxf(mx, s[t]); }
    float den = 0.f;
#pragma unroll
    for (int t = 0; t < 9; t++) { s[t] = __expf(s[t] - mx); den += s[t]; }
    float inv = 1.f / den;
#pragma unroll
    for (int t = 0; t < 9; t++) s[t] *= inv;

    // av = sum_t w_t * V[:, nt_t] (packed pairs)
    float2 avp[17];
#pragma unroll
    for (int i = 0; i < 17; i++) {
        float a0 = 0.f, a1 = 0.f;
#pragma unroll
        for (int t = 0; t < 9; t++) {
            a0 += s[t] * sm[OFF_V + (2 * i) * PITCH + nt[t]];
            a1 += s[t] * sm[OFF_V + (2 * i + 1) * PITCH + nt[t]];
        }
        avp[i] = make_float2(a0, a1);
    }

    // out_proj fused into fc_sa: sa[j] = sab[j] + sum_o saw[j][o]*(opb[o]+opw[o]·av)
    float sa[32];
#pragma unroll
    for (int j = 0; j < H; j++) sa[j] = sm[OFF_SAB + j];
#pragma unroll 1
    for (int o = 0; o < E; o++) {
        float oo = sm[OFF_OPB + o] + dot17(sm + OFF_OPW + o * E, avp);
#pragma unroll
        for (int j = 0; j < H; j++) sa[j] += oo * sm[OFF_SAW + j * E + o];
    }

    // residual with own (unshifted) h, pack for fc2
    const int own = (pr + 1) * HT + (pc + 1);
    float2 nh[16];
#pragma unroll
    for (int i = 0; i < 16; i++) {
        nh[i].x = sa[2 * i]     + sm[OFF_TOK + (2 * i) * PITCH + own];
        nh[i].y = sa[2 * i + 1] + sm[OFF_TOK + (2 * i + 1) * PITCH + own];
    }

    // fc2
    float y[32];
#pragma unroll
    for (int j = 0; j < H; j++)
        y[j] = sm[OFF_F2B + j] + dot16(sm + OFF_F2W + j * H, nh);

    // layernorm (eps 1e-5)
    float m = 0.f;
#pragma unroll
    for (int j = 0; j < H; j++) m += y[j];
    m *= (1.f / 32.f);
    float var = 0.f;
#pragma unroll
    for (int j = 0; j < H; j++) { float d0 = y[j] - m; var += d0 * d0; }
    float rs = rsqrtf(var * (1.f / 32.f) + 1e-5f);

    float* dn = dst + ((size_t)bb * P + (size_t)(gr * NSIDE + gc)) * H;
#pragma unroll
    for (int q4 = 0; q4 < 8; q4++) {
        float4 o4;
        o4.x = (y[4 * q4 + 0] - m) * rs * sm[OFF_LNG + 4 * q4 + 0] + sm[OFF_LNB + 4 * q4 + 0];
        o4.y = (y[4 * q4 + 1] - m) * rs * sm[OFF_LNG + 4 * q4 + 1] + sm[OFF_LNB + 4 * q4 + 1];
        o4.z = (y[4 * q4 + 2] - m) * rs * sm[OFF_LNG + 4 * q4 + 2] + sm[OFF_LNB + 4 * q4 + 2];
        o4.w = (y[4 * q4 + 3] - m) * rs * sm[OFF_LNG + 4 * q4 + 3] + sm[OFF_LNB + 4 * q4 + 3];
        reinterpret_cast<float4*>(dn)[q4] = o4;
    }
}

}  // namespace

extern "C" void kernel_launch(void* const* d_in, const int* in_sizes, int n_in,
                              void* d_out, int out_size) {
    const float* x   = (const float*)d_in[0];
    const float* ipw = (const float*)d_in[1];
    const float* ipb = (const float*)d_in[2];
    const float* opw = (const float*)d_in[3];
    const float* opb = (const float*)d_in[4];
    const float* saw = (const float*)d_in[5];
    const float* sab = (const float*)d_in[6];
    const float* f2w = (const float*)d_in[7];
    const float* f2b = (const float*)d_in[8];
    const float* lng = (const float*)d_in[9];
    const float* lnb = (const float*)d_in[10];
    float* out = (float*)d_out;

    cudaFuncSetAttribute(la_step, cudaFuncAttributeMaxDynamicSharedMemorySize,
                         (int)SMEM_BYTES);

    dim3 blk(256);
    // 10 observation steps: independent, one launch, grid.z indexes the step.
    la_step<<<dim3(16, 8, 10), blk, SMEM_BYTES>>>(
        x, out, ipw, ipb, opw, opb, saw, sab, f2w, f2b, lng, lnb);
    // 50 prediction steps: sequential rollout, each reads the previous slab.
    for (int t = 10; t < 60; t++) {
        la_step<<<dim3(16, 8, 1), blk, SMEM_BYTES>>>(
            out + (size_t)(t - 1) * NSTR, out + (size_t)t * NSTR,
            ipw, ipb, opw, opb, saw, sab, f2w, f2b, lng, lnb);
    }
    (void)in_sizes; (void)n_in; (void)out_size;
}

// round 6
// speedup vs baseline: 1.1982x; 1.1982x over previous
#include <cuda_runtime.h>

// LocalAttention rollout: 10 independent obs steps + 50 sequential pred steps.
// One fused kernel per step. CTA = 16x16 patch tile (+halo) for one batch,
// 512 threads (2 threads per patch, shfl-pair reductions).
// Phase 1 computes Q,K,V per halo token (Q hoisted out of phase 2).
// out_proj is folded into fc_sa offline: FW = saw@opw, fb = sab + saw@opb.

namespace {

constexpr int NSIDE = 64;
constexpr int P     = NSIDE * NSIDE;   // 4096 patches
constexpr int NB    = 8;               // batch
constexpr int H     = 32;              // hidden
constexpr int E     = 34;              // embed (H + 2 label dims)
constexpr size_t NSTR = (size_t)NB * P * H;   // elems per step slab

constexpr int TIL    = 16;             // tile side (patches)
constexpr int HT     = TIL + 2;        // halo side = 18
constexpr int TOKENS = HT * HT;        // 324 halo tokens
constexpr int PITCH  = 325;            // odd pitch: conflict-free smem
constexpr int NTHR   = 512;

// shared-memory layout (floats)
constexpr int OFF_TOK = 0;                         // [34][325] token (h + label)
constexpr int OFF_Q   = OFF_TOK + E * PITCH;       // [34][325] queries (w/ bias)
constexpr int OFF_K   = OFF_Q   + E * PITCH;       // [34][325] keys
constexpr int OFF_V   = OFF_K   + E * PITCH;       // [34][325] values
constexpr int OFF_IPW = OFF_V   + E * PITCH;       // in_proj_w (102x34)
constexpr int OFF_IPB = OFF_IPW + 3 * E * E;       // in_proj_b (102)
constexpr int OFF_FWT = OFF_IPB + 3 * E;           // fused (saw@opw)^T [34][32]
constexpr int OFF_FB  = OFF_FWT + E * H;           // fused bias (32)
constexpr int OFF_F2W = OFF_FB  + H;               // fc2_w (32x32)
constexpr int OFF_F2B = OFF_F2W + H * H;           // fc2_b (32)
constexpr int OFF_LNG = OFF_F2B + H;               // ln gamma (32)
constexpr int OFF_LNB = OFF_LNG + H;               // ln beta (32)
constexpr int SMEM_FLOATS = OFF_LNB + H;
constexpr size_t SMEM_BYTES = (size_t)SMEM_FLOATS * sizeof(float); // ~195.4 KB

__device__ float g_FWT[E * H];   // [o][j]  (saw@opw transposed)
__device__ float g_fb[H];        // sab + saw@opb

// packed dual-FMA (Blackwell f32x2 path — ptxas never emits this from C++)
__device__ __forceinline__ float2 ffma2(float2 a, float2 b, float2 c) {
    float2 d;
    asm("fma.rn.f32x2 %0, %1, %2, %3;"
        : "=l"(reinterpret_cast<unsigned long long&>(d))
        : "l"(reinterpret_cast<unsigned long long&>(a)),
          "l"(reinterpret_cast<unsigned long long&>(b)),
          "l"(reinterpret_cast<unsigned long long&>(c)));
    return d;
}

// dot of 34-float weight row (smem, 8B-aligned) with packed register vector
__device__ __forceinline__ float dot17(const float* w, const float2* v) {
    const float2* w2 = reinterpret_cast<const float2*>(w);
    float2 a0 = make_float2(0.f, 0.f), a1 = make_float2(0.f, 0.f);
#pragma unroll
    for (int i = 0; i < 16; i += 2) {
        a0 = ffma2(w2[i],     v[i],     a0);
        a1 = ffma2(w2[i + 1], v[i + 1], a1);
    }
    a0 = ffma2(w2[16], v[16], a0);
    return (a0.x + a1.x) + (a0.y + a1.y);
}

// dot of 32-float weight row with packed register vector
__device__ __forceinline__ float dot16(const float* w, const float2* v) {
    const float2* w2 = reinterpret_cast<const float2*>(w);
    float2 a0 = make_float2(0.f, 0.f), a1 = make_float2(0.f, 0.f);
#pragma unroll
    for (int i = 0; i < 16; i += 2) {
        a0 = ffma2(w2[i],     v[i],     a0);
        a1 = ffma2(w2[i + 1], v[i + 1], a1);
    }
    return (a0.x + a1.x) + (a0.y + a1.y);
}

__device__ __forceinline__ int clamp63(int v) {
    return v < 0 ? 0 : (v > NSIDE - 1 ? NSIDE - 1 : v);
}

// one-time weight fusion: FW^T[o][j] = sum_e saw[j][e]*opw[e][o]
__global__ void la_prep(const float* __restrict__ opw, const float* __restrict__ opb,
                        const float* __restrict__ saw, const float* __restrict__ sab)
{
    const int o = blockIdx.x;     // 0..33
    const int j = threadIdx.x;    // 0..31
    float acc = 0.f;
#pragma unroll
    for (int e = 0; e < E; e++) acc += saw[j * E + e] * opw[e * E + o];
    g_FWT[o * H + j] = acc;
    if (o == 0) {
        float b = sab[j];
#pragma unroll
        for (int e = 0; e < E; e++) b += saw[j * E + e] * opb[e];
        g_fb[j] = b;
    }
}

__global__ void __launch_bounds__(NTHR, 1)
la_step(const float* __restrict__ src, float* __restrict__ dst,
        const float* __restrict__ g_ipw, const float* __restrict__ g_ipb,
        const float* __restrict__ g_f2w, const float* __restrict__ g_f2b,
        const float* __restrict__ g_lng, const float* __restrict__ g_lnb)
{
    extern __shared__ float sm[];
    const int tid = threadIdx.x;
    src += (size_t)blockIdx.z * NSTR;
    dst += (size_t)blockIdx.z * NSTR;
    const int bb = blockIdx.y;
    const int tr = (int)(blockIdx.x >> 2) * TIL;   // tile origin row
    const int tc = (int)(blockIdx.x & 3) * TIL;    // tile origin col

    // ---- stage weights ----
#pragma unroll 1
    for (int i = tid; i < 3 * E * E; i += NTHR) sm[OFF_IPW + i] = g_ipw[i];
#pragma unroll 1
    for (int i = tid; i < E * H; i += NTHR)     sm[OFF_FWT + i] = g_FWT[i];
#pragma unroll 1
    for (int i = tid; i < H * H; i += NTHR)     sm[OFF_F2W + i] = g_f2w[i];
    if (tid < 3 * E) sm[OFF_IPB + tid] = g_ipb[tid];
    if (tid < H) {
        sm[OFF_FB  + tid] = g_fb[tid];
        sm[OFF_F2B + tid] = g_f2b[tid];
        sm[OFF_LNG + tid] = g_lng[tid];
        sm[OFF_LNB + tid] = g_lnb[tid];
    }

    // ---- load halo tokens (h + labels) into transposed smem ----
    const float* srcb = src + (size_t)bb * P * H;
#pragma unroll 1
    for (int j = tid; j < TOKENS * H; j += NTHR) {
        int t = j >> 5, d = j & 31;
        int hr = t / HT, hc = t - hr * HT;
        int gr = clamp63(tr - 1 + hr);
        int gc = clamp63(tc - 1 + hc);
        sm[OFF_TOK + d * PITCH + t] = srcb[(size_t)(gr * NSIDE + gc) * H + d];
    }
#pragma unroll 1
    for (int t = tid; t < TOKENS; t += NTHR) {
        int hr = t / HT, hc = t - hr * HT;
        int gr = clamp63(tr - 1 + hr);
        int gc = clamp63(tc - 1 + hc);
        sm[OFF_TOK + 32 * PITCH + t] = (float)gr * (1.f / 64.f);
        sm[OFF_TOK + 33 * PITCH + t] = (float)gc * (1.f / 64.f);
    }
    __syncthreads();

    // ---- phase 1: Q, K, V for every halo token ----
    // task = proj*324 + token, proj in {0:Q, 1:K, 2:V}
#pragma unroll 1
    for (int task = tid; task < 3 * TOKENS; task += NTHR) {
        int proj = task / TOKENS;
        int t = task - proj * TOKENS;
        float2 tp[17];
#pragma unroll
        for (int i = 0; i < 17; i++) {
            tp[i].x = sm[OFF_TOK + (2 * i) * PITCH + t];
            tp[i].y = sm[OFF_TOK + (2 * i + 1) * PITCH + t];
        }
        const float* wb = sm + OFF_IPW + proj * (E * E);
        const float* bbp = sm + OFF_IPB + proj * E;
        float* ob = sm + OFF_Q + proj * (E * PITCH);
#pragma unroll 1
        for (int o = 0; o < E; o++) {
            ob[o * PITCH + t] = bbp[o] + dot17(wb + o * E, tp);
        }
    }
    __syncthreads();

    // ---- phase 2: two threads per patch (shfl-pair reductions) ----
    const int p = tid >> 1, role = tid & 1;
    const int pr = p >> 4, pc = p & 15;
    const int gr = tr + pr, gc = tc + pc;
    // boundary-corrected neighborhood shift
    const int sr = (gr == 0) - (gr == NSIDE - 1);
    const int sc = (gc == 0) - (gc == NSIDE - 1);
    int nt[9];
#pragma unroll
    for (int dr = 0; dr < 3; dr++)
#pragma unroll
        for (int dc = 0; dc < 3; dc++)
            nt[dr * 3 + dc] = (pr + dr + sr) * HT + (pc + dc + sc);
    const int ct = nt[4];   // shifted center token (query source)

    // scores: s[t] = sum_o Q[o][ct] * K[o][nt_t]; o split across the pair
    float s[9];
#pragma unroll
    for (int t = 0; t < 9; t++) s[t] = 0.f;
    {
        const int ob0 = role * 17;
#pragma unroll 1
        for (int o = ob0; o < ob0 + 17; o++) {
            float qo = sm[OFF_Q + o * PITCH + ct];
#pragma unroll
            for (int t = 0; t < 9; t++) s[t] += qo * sm[OFF_K + o * PITCH + nt[t]];
        }
    }
#pragma unroll
    for (int t = 0; t < 9; t++) s[t] += __shfl_xor_sync(0xffffffffu, s[t], 1);

    // softmax over 9 (scaled by 1/sqrt(34)) — duplicated in both roles
    constexpr float ISQ = 0.17149858514250882f;
    float mx = s[0] * ISQ;
#pragma unroll
    for (int t = 0; t < 9; t++) { s[t] *= ISQ; mx = fmaxf(mx, s[t]); }
    float den = 0.f;
#pragma unroll
    for (int t = 0; t < 9; t++) { s[t] = __expf(s[t] - mx); den += s[t]; }
    float inv = 1.f / den;
#pragma unroll
    for (int t = 0; t < 9; t++) s[t] *= inv;

    // av: role 0 owns dim-pairs i in [0,9), role 1 i in [9,17)
    const int i0 = role ? 9 : 0;
    const int ni = role ? 8 : 9;
    float2 avp[9];
#pragma unroll 1
    for (int k = 0; k < ni; k++) {
        int i = i0 + k;
        float a0 = 0.f, a1 = 0.f;
#pragma unroll
        for (int t = 0; t < 9; t++) {
            a0 += s[t] * sm[OFF_V + (2 * i) * PITCH + nt[t]];
            a1 += s[t] * sm[OFF_V + (2 * i + 1) * PITCH + nt[t]];
        }
        avp[k] = make_float2(a0, a1);
    }

    // fused fc_sa: sa[j] = fb[j] + sum_o FW[j][o]*av[o]; o split by role
    float2 sa2[16];
#pragma unroll
    for (int j = 0; j < 16; j++) sa2[j] = make_float2(0.f, 0.f);
#pragma unroll 1
    for (int k = 0; k < ni; k++) {
        int i = i0 + k;
        const float2* w0 = reinterpret_cast<const float2*>(sm + OFF_FWT + (2 * i) * H);
        const float2* w1 = reinterpret_cast<const float2*>(sm + OFF_FWT + (2 * i + 1) * H);
        float2 ax = make_float2(avp[k].x, avp[k].x);
        float2 ay = make_float2(avp[k].y, avp[k].y);
#pragma unroll
        for (int j = 0; j < 16; j++) {
            sa2[j] = ffma2(w0[j], ax, sa2[j]);
            sa2[j] = ffma2(w1[j], ay, sa2[j]);
        }
    }
#pragma unroll
    for (int j = 0; j < 16; j++) {
        sa2[j].x += __shfl_xor_sync(0xffffffffu, sa2[j].x, 1);
        sa2[j].y += __shfl_xor_sync(0xffffffffu, sa2[j].y, 1);
    }

    // residual with own (unshifted) h + fused bias
    const int own = (pr + 1) * HT + (pc + 1);
    const float2* fb2 = reinterpret_cast<const float2*>(sm + OFF_FB);
    float2 nh[16];
#pragma unroll
    for (int j = 0; j < 16; j++) {
        float2 b2 = fb2[j];
        nh[j].x = sa2[j].x + b2.x + sm[OFF_TOK + (2 * j) * PITCH + own];
        nh[j].y = sa2[j].y + b2.y + sm[OFF_TOK + (2 * j + 1) * PITCH + own];
    }

    // fc2: output rows split by role (16 each)
    const int jb = role * 16;
    float y[16];
#pragma unroll
    for (int k = 0; k < 16; k++)
        y[k] = sm[OFF_F2B + jb + k] + dot16(sm + OFF_F2W + (jb + k) * H, nh);

    // layernorm (eps 1e-5) — pairwise reduction
    float sum = 0.f;
#pragma unroll
    for (int k = 0; k < 16; k++) sum += y[k];
    sum += __shfl_xor_sync(0xffffffffu, sum, 1);
    float m = sum * (1.f / 32.f);
    float var = 0.f;
#pragma unroll
    for (int k = 0; k < 16; k++) { float d0 = y[k] - m; var += d0 * d0; }
    var += __shfl_xor_sync(0xffffffffu, var, 1);
    float rs = rsqrtf(var * (1.f / 32.f) + 1e-5f);

    float* dn = dst + ((size_t)bb * P + (size_t)(gr * NSIDE + gc)) * H + jb;
#pragma unroll
    for (int q4 = 0; q4 < 4; q4++) {
        float4 o4;
        o4.x = (y[4 * q4 + 0] - m) * rs * sm[OFF_LNG + jb + 4 * q4 + 0] + sm[OFF_LNB + jb + 4 * q4 + 0];
        o4.y = (y[4 * q4 + 1] - m) * rs * sm[OFF_LNG + jb + 4 * q4 + 1] + sm[OFF_LNB + jb + 4 * q4 + 1];
        o4.z = (y[4 * q4 + 2] - m) * rs * sm[OFF_LNG + jb + 4 * q4 + 2] + sm[OFF_LNB + jb + 4 * q4 + 2];
        o4.w = (y[4 * q4 + 3] - m) * rs * sm[OFF_LNG + jb + 4 * q4 + 3] + sm[OFF_LNB + jb + 4 * q4 + 3];
        reinterpret_cast<float4*>(dn)[q4] = o4;
    }
}

}  // namespace

extern "C" void kernel_launch(void* const* d_in, const int* in_sizes, int n_in,
                              void* d_out, int out_size) {
    const float* x   = (const float*)d_in[0];
    const float* ipw = (const float*)d_in[1];
    const float* ipb = (const float*)d_in[2];
    const float* opw = (const float*)d_in[3];
    const float* opb = (const float*)d_in[4];
    const float* saw = (const float*)d_in[5];
    const float* sab = (const float*)d_in[6];
    const float* f2w = (const float*)d_in[7];
    const float* f2b = (const float*)d_in[8];
    const float* lng = (const float*)d_in[9];
    const float* lnb = (const float*)d_in[10];
    float* out = (float*)d_out;

    cudaFuncSetAttribute(la_step, cudaFuncAttributeMaxDynamicSharedMemorySize,
                         (int)SMEM_BYTES);

    // one-time weight fusion (recomputed every call — deterministic)
    la_prep<<<E, H>>>(opw, opb, saw, sab);

    dim3 blk(NTHR);
    // 10 observation steps: independent, one launch, grid.z indexes the step.
    la_step<<<dim3(16, 8, 10), blk, SMEM_BYTES>>>(
        x, out, ipw, ipb, f2w, f2b, lng, lnb);
    // 50 prediction steps: sequential rollout.
    for (int t = 10; t < 60; t++) {
        la_step<<<dim3(16, 8, 1), blk, SMEM_BYTES>>>(
            out + (size_t)(t - 1) * NSTR, out + (size_t)t * NSTR,
            ipw, ipb, f2w, f2b, lng, lnb);
    }
    (void)in_sizes; (void)n_in; (void)out_size;
}

// round 7
// speedup vs baseline: 1.3917x; 1.1615x over previous
#include <cuda_runtime.h>

// LocalAttention rollout: 10 independent obs steps + 50 sequential pred steps.
// CTA = 16x8 patch tile (+halo) for one batch, 256 threads, 2 CTAs/SM.
// Phase 1: pair-tasks compute Q (interior only), K, V per halo token, reading
// h directly from global (L2-hot); weights shared across the token pair.
// Phase 2: 2 threads per patch, shfl-pair reductions.
// out_proj folded into fc_sa offline: FW = saw@opw, fb = sab + saw@opb.

namespace {

constexpr int NSIDE = 64;
constexpr int P     = NSIDE * NSIDE;   // 4096 patches
constexpr int NB    = 8;               // batch
constexpr int H     = 32;              // hidden
constexpr int E     = 34;              // embed (H + 2 label dims)
constexpr size_t NSTR = (size_t)NB * P * H;   // elems per step slab

constexpr int TR     = 16;             // tile rows (patches)
constexpr int TC     = 8;              // tile cols
constexpr int HRW    = TR + 2;         // halo rows = 18
constexpr int HC     = TC + 2;         // halo cols = 10
constexpr int TOKENS = HRW * HC;       // 180 halo tokens
constexpr int PIT    = 181;            // odd pitch: conflict-free smem
constexpr int NQ     = TR * TC;        // 128 interior tokens (Q needed only here)
constexpr int QPIT   = 129;
constexpr int NTHR   = 256;

// shared-memory layout (floats)
constexpr int OFF_K   = 0;                         // [34][181] keys
constexpr int OFF_V   = OFF_K   + E * PIT;         // [34][181] values
constexpr int OFF_Q   = OFF_V   + E * PIT;         // [34][129] queries (interior)
constexpr int OFF_IPW = OFF_Q   + E * QPIT;        // in_proj_w (102x34)
constexpr int OFF_IPB = OFF_IPW + 3 * E * E;       // in_proj_b (102)
constexpr int OFF_FWT = OFF_IPB + 3 * E;           // fused (saw@opw)^T [34][32]
constexpr int OFF_FB  = OFF_FWT + E * H;           // fused bias (32)
constexpr int OFF_F2W = OFF_FB  + H;               // fc2_w (32x32)
constexpr int OFF_F2B = OFF_F2W + H * H;           // fc2_b (32)
constexpr int OFF_LNG = OFF_F2B + H;               // ln gamma (32)
constexpr int OFF_LNB = OFF_LNG + H;               // ln beta (32)
constexpr int SMEM_FLOATS = OFF_LNB + H;           // 22504 floats
constexpr size_t SMEM_BYTES = (size_t)SMEM_FLOATS * sizeof(float); // 90,016 B

__device__ float g_FWT[E * H];   // [o][j]  (saw@opw transposed)
__device__ float g_fb[H];        // sab + saw@opb

// packed dual-FMA (Blackwell f32x2 path — ptxas never emits this from C++)
__device__ __forceinline__ float2 ffma2(float2 a, float2 b, float2 c) {
    float2 d;
    asm("fma.rn.f32x2 %0, %1, %2, %3;"
        : "=l"(reinterpret_cast<unsigned long long&>(d))
        : "l"(reinterpret_cast<unsigned long long&>(a)),
          "l"(reinterpret_cast<unsigned long long&>(b)),
          "l"(reinterpret_cast<unsigned long long&>(c)));
    return d;
}

// dot of 32-float weight row with packed register vector
__device__ __forceinline__ float dot16(const float* w, const float2* v) {
    const float2* w2 = reinterpret_cast<const float2*>(w);
    float2 a0 = make_float2(0.f, 0.f), a1 = make_float2(0.f, 0.f);
#pragma unroll
    for (int i = 0; i < 16; i += 2) {
        a0 = ffma2(w2[i],     v[i],     a0);
        a1 = ffma2(w2[i + 1], v[i + 1], a1);
    }
    return (a0.x + a1.x) + (a0.y + a1.y);
}

__device__ __forceinline__ int clamp63(int v) {
    return v < 0 ? 0 : (v > NSIDE - 1 ? NSIDE - 1 : v);
}

// one-time weight fusion: FW^T[o][j] = sum_e saw[j][e]*opw[e][o]
__global__ void la_prep(const float* __restrict__ opw, const float* __restrict__ opb,
                        const float* __restrict__ saw, const float* __restrict__ sab)
{
    const int o = blockIdx.x;     // 0..33
    const int j = threadIdx.x;    // 0..31
    float acc = 0.f;
#pragma unroll
    for (int e = 0; e < E; e++) acc += saw[j * E + e] * opw[e * E + o];
    g_FWT[o * H + j] = acc;
    if (o == 0) {
        float b = sab[j];
#pragma unroll
        for (int e = 0; e < E; e++) b += saw[j * E + e] * opb[e];
        g_fb[j] = b;
    }
}

__global__ void __launch_bounds__(NTHR, 2)
la_step(const float* __restrict__ src, float* __restrict__ dst,
        const float* __restrict__ g_ipw, const float* __restrict__ g_ipb,
        const float* __restrict__ g_f2w, const float* __restrict__ g_f2b,
        const float* __restrict__ g_lng, const float* __restrict__ g_lnb)
{
    extern __shared__ float sm[];
    const int tid = threadIdx.x;
    src += (size_t)blockIdx.z * NSTR;
    dst += (size_t)blockIdx.z * NSTR;
    const int bb = blockIdx.y;
    const int tr = (int)(blockIdx.x >> 3) * TR;    // tile origin row (4 row-tiles)
    const int tc = (int)(blockIdx.x & 7) * TC;     // tile origin col (8 col-tiles)
    const float* srcb = src + (size_t)bb * P * H;

    // ---- stage weights ----
#pragma unroll 1
    for (int i = tid; i < 3 * E * E; i += NTHR) sm[OFF_IPW + i] = g_ipw[i];
#pragma unroll 1
    for (int i = tid; i < E * H; i += NTHR)     sm[OFF_FWT + i] = g_FWT[i];
#pragma unroll 1
    for (int i = tid; i < H * H; i += NTHR)     sm[OFF_F2W + i] = g_f2w[i];
    if (tid < 3 * E) sm[OFF_IPB + tid] = g_ipb[tid];
    if (tid < H) {
        sm[OFF_FB  + tid] = g_fb[tid];
        sm[OFF_F2B + tid] = g_f2b[tid];
        sm[OFF_LNG + tid] = g_lng[tid];
        sm[OFF_LNB + tid] = g_lnb[tid];
    }
    __syncthreads();

    // ---- phase 1: pair-tasks. tasks 0..89 K, 90..179 V, 180..243 Q(interior).
    // Each task projects TWO tokens sharing every weight load.
    if (tid < 180 + NQ / 2) {
        int tA, tB;                 // store indices within target plane
        int grA, gcA, grB, gcB;     // global patch coords of the two tokens
        float* ob; int pit; int wrow;
        if (tid < 180) {
            const int proj = (tid < 90) ? 1 : 2;       // 1=K, 2=V
            const int m = tid - (proj - 1) * 90;
            tA = m; tB = m + 90;
            int hr = tA / HC, hc = tA - hr * HC;
            grA = clamp63(tr - 1 + hr); gcA = clamp63(tc - 1 + hc);
            hr = tB / HC; hc = tB - hr * HC;
            grB = clamp63(tr - 1 + hr); gcB = clamp63(tc - 1 + hc);
            ob = sm + (proj == 1 ? OFF_K : OFF_V); pit = PIT;
            wrow = proj * E;
        } else {
            const int m = tid - 180;
            tA = m; tB = m + NQ / 2;
            grA = tr + (tA >> 3); gcA = tc + (tA & 7);
            grB = tr + (tB >> 3); gcB = tc + (tB & 7);
            ob = sm + OFF_Q; pit = QPIT;
            wrow = 0;
        }
        // load both tokens (32 h dims + 2 label dims) into packed registers
        float2 a[17], b[17];
        {
            const float4* pA = reinterpret_cast<const float4*>(
                srcb + (size_t)(grA * NSIDE + gcA) * H);
            const float4* pB = reinterpret_cast<const float4*>(
                srcb + (size_t)(grB * NSIDE + gcB) * H);
#pragma unroll
            for (int i = 0; i < 8; i++) {
                float4 v = pA[i];
                a[2 * i]     = make_float2(v.x, v.y);
                a[2 * i + 1] = make_float2(v.z, v.w);
                float4 u = pB[i];
                b[2 * i]     = make_float2(u.x, u.y);
                b[2 * i + 1] = make_float2(u.z, u.w);
            }
            a[16] = make_float2((float)grA * (1.f / 64.f), (float)gcA * (1.f / 64.f));
            b[16] = make_float2((float)grB * (1.f / 64.f), (float)gcB * (1.f / 64.f));
        }
        const float* wb = sm + OFF_IPW + wrow * E;
        const float* bp = sm + OFF_IPB + wrow;
#pragma unroll 1
        for (int o = 0; o < E; o++) {
            const float2* w2 = reinterpret_cast<const float2*>(wb + o * E);
            float2 sA0 = make_float2(0.f, 0.f), sA1 = make_float2(0.f, 0.f);
            float2 sB0 = make_float2(0.f, 0.f), sB1 = make_float2(0.f, 0.f);
#pragma unroll
            for (int i = 0; i < 16; i += 2) {
                float2 w0 = w2[i], w1 = w2[i + 1];
                sA0 = ffma2(w0, a[i],     sA0);
                sB0 = ffma2(w0, b[i],     sB0);
                sA1 = ffma2(w1, a[i + 1], sA1);
                sB1 = ffma2(w1, b[i + 1], sB1);
            }
            float2 wl = w2[16];
            sA0 = ffma2(wl, a[16], sA0);
            sB0 = ffma2(wl, b[16], sB0);
            const float bv = bp[o];
            ob[o * pit + tA] = bv + (sA0.x + sA1.x) + (sA0.y + sA1.y);
            ob[o * pit + tB] = bv + (sB0.x + sB1.x) + (sB0.y + sB1.y);
        }
    }
    __syncthreads();

    // ---- phase 2: two threads per patch (shfl-pair reductions) ----
    const int p = tid >> 1, role = tid & 1;
    const int pr = p >> 3, pc = p & 7;
    const int gr = tr + pr, gc = tc + pc;
    // boundary-corrected neighborhood shift
    const int sr = (gr == 0) - (gr == NSIDE - 1);
    const int sc = (gc == 0) - (gc == NSIDE - 1);
    int nt[9];
#pragma unroll
    for (int dr = 0; dr < 3; dr++)
#pragma unroll
        for (int dc = 0; dc < 3; dc++)
            nt[dr * 3 + dc] = (pr + dr + sr) * HC + (pc + dc + sc);
    const int qct = (pr + sr) * TC + (pc + sc);   // shifted center, interior index

    // own-token h (residual), full 32 dims — L1/L2-hot global read
    float hv[32];
    {
        const float4* ph = reinterpret_cast<const float4*>(
            srcb + (size_t)(gr * NSIDE + gc) * H);
#pragma unroll
        for (int i = 0; i < 8; i++) {
            float4 v = ph[i];
            hv[4 * i] = v.x; hv[4 * i + 1] = v.y;
            hv[4 * i + 2] = v.z; hv[4 * i + 3] = v.w;
        }
    }

    // scores: s[t] = sum_o Q[o][qct] * K[o][nt_t]; o split across the pair
    float s[9];
#pragma unroll
    for (int t = 0; t < 9; t++) s[t] = 0.f;
    {
        const int ob0 = role * 17;
#pragma unroll 1
        for (int o = ob0; o < ob0 + 17; o++) {
            float qo = sm[OFF_Q + o * QPIT + qct];
#pragma unroll
            for (int t = 0; t < 9; t++) s[t] += qo * sm[OFF_K + o * PIT + nt[t]];
        }
    }
#pragma unroll
    for (int t = 0; t < 9; t++) s[t] += __shfl_xor_sync(0xffffffffu, s[t], 1);

    // softmax over 9 (scaled by 1/sqrt(34)) — duplicated in both roles
    constexpr float ISQ = 0.17149858514250882f;
    float mx = s[0] * ISQ;
#pragma unroll
    for (int t = 0; t < 9; t++) { s[t] *= ISQ; mx = fmaxf(mx, s[t]); }
    float den = 0.f;
#pragma unroll
    for (int t = 0; t < 9; t++) { s[t] = __expf(s[t] - mx); den += s[t]; }
    float inv = 1.f / den;
#pragma unroll
    for (int t = 0; t < 9; t++) s[t] *= inv;

    // av: role 0 owns dim-pairs i in [0,9), role 1 i in [9,17)
    const int i0 = role ? 9 : 0;
    const int ni = role ? 8 : 9;
    float2 avp[9];
#pragma unroll 1
    for (int k = 0; k < ni; k++) {
        int i = i0 + k;
        float a0 = 0.f, a1 = 0.f;
#pragma unroll
        for (int t = 0; t < 9; t++) {
            a0 += s[t] * sm[OFF_V + (2 * i) * PIT + nt[t]];
            a1 += s[t] * sm[OFF_V + (2 * i + 1) * PIT + nt[t]];
        }
        avp[k] = make_float2(a0, a1);
    }

    // fused fc_sa: sa[j] = fb[j] + sum_o FW[j][o]*av[o]; o split by role
    float2 sa2[16];
#pragma unroll
    for (int j = 0; j < 16; j++) sa2[j] = make_float2(0.f, 0.f);
#pragma unroll 1
    for (int k = 0; k < ni; k++) {
        int i = i0 + k;
        const float2* w0 = reinterpret_cast<const float2*>(sm + OFF_FWT + (2 * i) * H);
        const float2* w1 = reinterpret_cast<const float2*>(sm + OFF_FWT + (2 * i + 1) * H);
        float2 ax = make_float2(avp[k].x, avp[k].x);
        float2 ay = make_float2(avp[k].y, avp[k].y);
#pragma unroll
        for (int j = 0; j < 16; j++) {
            sa2[j] = ffma2(w0[j], ax, sa2[j]);
            sa2[j] = ffma2(w1[j], ay, sa2[j]);
        }
    }
#pragma unroll
    for (int j = 0; j < 16; j++) {
        sa2[j].x += __shfl_xor_sync(0xffffffffu, sa2[j].x, 1);
        sa2[j].y += __shfl_xor_sync(0xffffffffu, sa2[j].y, 1);
    }

    // residual with own h + fused bias
    const float2* fb2 = reinterpret_cast<const float2*>(sm + OFF_FB);
    float2 nh[16];
#pragma unroll
    for (int j = 0; j < 16; j++) {
        float2 b2 = fb2[j];
        nh[j].x = sa2[j].x + b2.x + hv[2 * j];
        nh[j].y = sa2[j].y + b2.y + hv[2 * j + 1];
    }

    // fc2: output rows split by role (16 each)
    const int jb = role * 16;
    float y[16];
#pragma unroll
    for (int k = 0; k < 16; k++)
        y[k] = sm[OFF_F2B + jb + k] + dot16(sm + OFF_F2W + (jb + k) * H, nh);

    // layernorm (eps 1e-5) — pairwise reduction
    float sum = 0.f;
#pragma unroll
    for (int k = 0; k < 16; k++) sum += y[k];
    sum += __shfl_xor_sync(0xffffffffu, sum, 1);
    float m = sum * (1.f / 32.f);
    float var = 0.f;
#pragma unroll
    for (int k = 0; k < 16; k++) { float d0 = y[k] - m; var += d0 * d0; }
    var += __shfl_xor_sync(0xffffffffu, var, 1);
    float rs = rsqrtf(var * (1.f / 32.f) + 1e-5f);

    float* dn = dst + ((size_t)bb * P + (size_t)(gr * NSIDE + gc)) * H + jb;
#pragma unroll
    for (int q4 = 0; q4 < 4; q4++) {
        float4 o4;
        o4.x = (y[4 * q4 + 0] - m) * rs * sm[OFF_LNG + jb + 4 * q4 + 0] + sm[OFF_LNB + jb + 4 * q4 + 0];
        o4.y = (y[4 * q4 + 1] - m) * rs * sm[OFF_LNG + jb + 4 * q4 + 1] + sm[OFF_LNB + jb + 4 * q4 + 1];
        o4.z = (y[4 * q4 + 2] - m) * rs * sm[OFF_LNG + jb + 4 * q4 + 2] + sm[OFF_LNB + jb + 4 * q4 + 2];
        o4.w = (y[4 * q4 + 3] - m) * rs * sm[OFF_LNG + jb + 4 * q4 + 3] + sm[OFF_LNB + jb + 4 * q4 + 3];
        reinterpret_cast<float4*>(dn)[q4] = o4;
    }
}

}  // namespace

extern "C" void kernel_launch(void* const* d_in, const int* in_sizes, int n_in,
                              void* d_out, int out_size) {
    const float* x   = (const float*)d_in[0];
    const float* ipw = (const float*)d_in[1];
    const float* ipb = (const float*)d_in[2];
    const float* opw = (const float*)d_in[3];
    const float* opb = (const float*)d_in[4];
    const float* saw = (const float*)d_in[5];
    const float* sab = (const float*)d_in[6];
    const float* f2w = (const float*)d_in[7];
    const float* f2b = (const float*)d_in[8];
    const float* lng = (const float*)d_in[9];
    const float* lnb = (const float*)d_in[10];
    float* out = (float*)d_out;

    cudaFuncSetAttribute(la_step, cudaFuncAttributeMaxDynamicSharedMemorySize,
                         (int)SMEM_BYTES);

    // one-time weight fusion (recomputed every call — deterministic)
    la_prep<<<E, H>>>(opw, opb, saw, sab);

    dim3 blk(NTHR);
    // 10 observation steps: independent, one launch, grid.z indexes the step.
    la_step<<<dim3(32, 8, 10), blk, SMEM_BYTES>>>(
        x, out, ipw, ipb, f2w, f2b, lng, lnb);
    // 50 prediction steps: sequential rollout.
    for (int t = 10; t < 60; t++) {
        la_step<<<dim3(32, 8, 1), blk, SMEM_BYTES>>>(
            out + (size_t)(t - 1) * NSTR, out + (size_t)t * NSTR,
            ipw, ipb, f2w, f2b, lng, lnb);
    }
    (void)in_sizes; (void)n_in; (void)out_size;
}